// round 1
// baseline (speedup 1.0000x reference)
#include <cuda_runtime.h>
#include <cuda_bf16.h>
#include <cstdint>

#define N_CELLS_MAX 50048
#define N_EDGES_MAX 1600512
#define C 64

// Scratch (allocation-free rule: __device__ globals)
__device__ float g_msg[N_CELLS_MAX * C];
__device__ float g_as[N_CELLS_MAX];
__device__ float g_ad[N_CELLS_MAX];
__device__ float g_rowsum[N_CELLS_MAX];
__device__ float g_e[N_EDGES_MAX];

__device__ __forceinline__ void red_add_v4(float* addr, float4 v) {
    asm volatile("red.global.add.v4.f32 [%0], {%1, %2, %3, %4};"
                 :: "l"(addr), "f"(v.x), "f"(v.y), "f"(v.z), "f"(v.w)
                 : "memory");
}

// Kernel 1: msg = x @ W ; alpha_src = msg @ a[:64] ; alpha_dst = msg @ a[64:]
// Also zeroes rowsum and out. One warp per row; each lane owns channels lane, lane+32.
__global__ void __launch_bounds__(256) k_gemm_alpha(
    const float* __restrict__ x, const float* __restrict__ W,
    const float* __restrict__ a, float* __restrict__ out, int n)
{
    __shared__ float Ws[C * C];
    __shared__ float As[2 * C];
    int tid = threadIdx.x;
    for (int i = tid; i < C * C; i += blockDim.x) Ws[i] = W[i];
    if (tid < 2 * C) As[tid] = a[tid];
    __syncthreads();

    int warp = tid >> 5, lane = tid & 31;
    int row = blockIdx.x * (blockDim.x >> 5) + warp;
    if (row >= n) return;

    const float* xr = x + (size_t)row * C;
    float xr0 = xr[lane];
    float xr1 = xr[lane + 32];
    float acc0 = 0.f, acc1 = 0.f;
    #pragma unroll
    for (int k = 0; k < 32; k++) {
        float xv = __shfl_sync(0xffffffffu, xr0, k);
        acc0 = fmaf(xv, Ws[k * C + lane],      acc0);
        acc1 = fmaf(xv, Ws[k * C + lane + 32], acc1);
    }
    #pragma unroll
    for (int k = 0; k < 32; k++) {
        float xv = __shfl_sync(0xffffffffu, xr1, k);
        acc0 = fmaf(xv, Ws[(k + 32) * C + lane],      acc0);
        acc1 = fmaf(xv, Ws[(k + 32) * C + lane + 32], acc1);
    }
    g_msg[(size_t)row * C + lane]      = acc0;
    g_msg[(size_t)row * C + lane + 32] = acc1;

    float s0 = acc0 * As[lane]       + acc1 * As[lane + 32];
    float s1 = acc0 * As[C + lane]   + acc1 * As[C + lane + 32];
    #pragma unroll
    for (int o = 16; o > 0; o >>= 1) {
        s0 += __shfl_xor_sync(0xffffffffu, s0, o);
        s1 += __shfl_xor_sync(0xffffffffu, s1, o);
    }
    if (lane == 0) {
        g_as[row] = s0;
        g_ad[row] = s1;
        g_rowsum[row] = 0.f;
    }
    out[(size_t)row * C + lane]      = 0.f;
    out[(size_t)row * C + lane + 32] = 0.f;
}

// Kernel 2: e = LeakyReLU(alpha_src[src] + alpha_dst[dst]); rowsum[src] += e
__global__ void __launch_bounds__(256) k_edge_e(
    const int* __restrict__ src, const int* __restrict__ dst, int E)
{
    int i = blockIdx.x * blockDim.x + threadIdx.x;
    if (i >= E) return;
    int s = src[i], d = dst[i];
    float v = g_as[s] + g_ad[d];
    float e = v > 0.f ? v : 0.2f * v;
    g_e[i] = e;
    atomicAdd(&g_rowsum[s], e);
}

// Kernel 3: out[src] += (e/rowsum[src] * edge_value) * msg[dst]
// Two edges per warp (16 lanes each); each lane handles one float4 (4 channels).
__global__ void __launch_bounds__(256) k_scatter(
    const int* __restrict__ src, const int* __restrict__ dst,
    const float* __restrict__ ev, float* __restrict__ out, int E)
{
    int lane = threadIdx.x & 31;
    int g = lane >> 4;       // which edge of this warp's pair
    int gl = lane & 15;      // float4 chunk within the 64-channel row
    long long warpGlobal = (long long)(blockIdx.x * blockDim.x + threadIdx.x) >> 5;
    long long e = warpGlobal * 2 + g;
    bool active = (e < E);

    int s = 0, d = 0;
    float coef = 0.f;
    if (active && gl == 0) {
        s = src[e];
        d = dst[e];
        coef = g_e[e] / g_rowsum[s] * ev[e];
    }
    int srcLane = g * 16;
    s    = __shfl_sync(0xffffffffu, s, srcLane);
    d    = __shfl_sync(0xffffffffu, d, srcLane);
    coef = __shfl_sync(0xffffffffu, coef, srcLane);
    if (!active) return;

    const float4 m = *reinterpret_cast<const float4*>(&g_msg[(size_t)d * C + gl * 4]);
    float4 r = make_float4(coef * m.x, coef * m.y, coef * m.z, coef * m.w);
    red_add_v4(&out[(size_t)s * C + gl * 4], r);
}

extern "C" void kernel_launch(void* const* d_in, const int* in_sizes, int n_in,
                              void* d_out, int out_size)
{
    const float* x_source   = (const float*)d_in[0];   // [n, 64]
    const int*   edge_index = (const int*)d_in[1];     // [2, E]
    const float* edge_vals  = (const float*)d_in[2];   // [E]
    const float* W          = (const float*)d_in[3];   // [64, 64]
    const float* a          = (const float*)d_in[4];   // [128]
    float* out = (float*)d_out;

    int n = in_sizes[0] / C;
    int E = in_sizes[2];
    const int* src = edge_index;
    const int* dst = edge_index + E;

    // K1: one warp/row, 8 rows per 256-thread block
    int blocks1 = (n + 7) / 8;
    k_gemm_alpha<<<blocks1, 256>>>(x_source, W, a, out, n);

    // K2: one thread/edge
    int blocks2 = (E + 255) / 256;
    k_edge_e<<<blocks2, 256>>>(src, dst, E);

    // K3: two edges per warp -> 16 edges per 256-thread block
    int blocks3 = (E + 15) / 16;
    k_scatter<<<blocks3, 256>>>(src, dst, edge_vals, out, E);
}

// round 6
// speedup vs baseline: 1.1520x; 1.1520x over previous
#include <cuda_runtime.h>
#include <cstdint>

#define N_CELLS_MAX 50048
#define N_EDGES_MAX 1600512
#define C 64

// Scratch (allocation-free rule: __device__ globals)
__device__ float g_msg[N_CELLS_MAX * C];
__device__ float g_as[N_CELLS_MAX];
__device__ float g_ad[N_CELLS_MAX];
__device__ float g_rowsum[N_CELLS_MAX];
__device__ float g_e[N_EDGES_MAX];

__device__ __forceinline__ void red_add_v4(float* addr, float4 v) {
    asm volatile("red.global.add.v4.f32 [%0], {%1, %2, %3, %4};"
                 :: "l"(addr), "f"(v.x), "f"(v.y), "f"(v.z), "f"(v.w)
                 : "memory");
}

// ---------------------------------------------------------------------------
// K1: msg = x @ W ; alpha_src = msg @ a[:64] ; alpha_dst = msg @ a[64:]
// ARITHMETIC IDENTICAL TO R1 (the passing kernel): per row, each lane owns
// channels (lane, lane+32); acc0/acc1 accumulate k=0..63 via the same
// fmaf(shfl(xr,k), Ws[k*C+lane], .) sequence; alpha via the same 32-lane
// butterfly of acc0*As[lane] + acc1*As[lane+32].
// PERF CHANGE ONLY: 4 rows per warp, so each LDS of Ws[k*C+lane] (row-
// invariant) is reused by 4 rows -> 4x less smem traffic (was 82.5% L1 SOL).
// ---------------------------------------------------------------------------
__global__ void __launch_bounds__(256) k_gemm_alpha(
    const float* __restrict__ x, const float* __restrict__ W,
    const float* __restrict__ a, float* __restrict__ out, int n)
{
    __shared__ float Ws[C * C];
    __shared__ float As[2 * C];
    int tid = threadIdx.x;
    for (int i = tid; i < C * C; i += blockDim.x) Ws[i] = W[i];
    if (tid < 2 * C) As[tid] = a[tid];
    __syncthreads();

    int warp = tid >> 5, lane = tid & 31;
    int row0 = (blockIdx.x * 8 + warp) * 4;    // 4 consecutive rows per warp
    if (row0 >= n) return;

    float xr0[4], xr1[4];
    #pragma unroll
    for (int r = 0; r < 4; r++) {
        int row = row0 + r;
        if (row < n) {
            const float* xr = x + (size_t)row * C;
            xr0[r] = xr[lane];
            xr1[r] = xr[lane + 32];
        } else {
            xr0[r] = 0.f;
            xr1[r] = 0.f;
        }
    }

    float acc0[4] = {0.f, 0.f, 0.f, 0.f};
    float acc1[4] = {0.f, 0.f, 0.f, 0.f};
    #pragma unroll
    for (int k = 0; k < 32; k++) {
        float w0 = Ws[k * C + lane];
        float w1 = Ws[k * C + lane + 32];
        #pragma unroll
        for (int r = 0; r < 4; r++) {
            float xv = __shfl_sync(0xffffffffu, xr0[r], k);
            acc0[r] = fmaf(xv, w0, acc0[r]);
            acc1[r] = fmaf(xv, w1, acc1[r]);
        }
    }
    #pragma unroll
    for (int k = 0; k < 32; k++) {
        float w0 = Ws[(k + 32) * C + lane];
        float w1 = Ws[(k + 32) * C + lane + 32];
        #pragma unroll
        for (int r = 0; r < 4; r++) {
            float xv = __shfl_sync(0xffffffffu, xr1[r], k);
            acc0[r] = fmaf(xv, w0, acc0[r]);
            acc1[r] = fmaf(xv, w1, acc1[r]);
        }
    }

    #pragma unroll
    for (int r = 0; r < 4; r++) {
        int row = row0 + r;
        bool ok = (row < n);
        if (ok) {
            g_msg[(size_t)row * C + lane]      = acc0[r];
            g_msg[(size_t)row * C + lane + 32] = acc1[r];
            out[(size_t)row * C + lane]      = 0.f;
            out[(size_t)row * C + lane + 32] = 0.f;
        }
        // Same expression and same 32-lane butterfly as R1.
        float s0 = acc0[r] * As[lane]     + acc1[r] * As[lane + 32];
        float s1 = acc0[r] * As[C + lane] + acc1[r] * As[C + lane + 32];
        #pragma unroll
        for (int o = 16; o > 0; o >>= 1) {
            s0 += __shfl_xor_sync(0xffffffffu, s0, o);
            s1 += __shfl_xor_sync(0xffffffffu, s1, o);
        }
        if (lane == 0 && ok) {
            g_as[row] = s0;
            g_ad[row] = s1;
            g_rowsum[row] = 0.f;
        }
    }
}

// ---------------------------------------------------------------------------
// K2: e = LeakyReLU(as[src] + ad[dst]); store e; rowsum[src] += e
// IDENTICAL to R1 (scalar, one thread per edge, same launch shape).
// ---------------------------------------------------------------------------
__global__ void __launch_bounds__(256) k_edge_e(
    const int* __restrict__ src, const int* __restrict__ dst, int E)
{
    int i = blockIdx.x * blockDim.x + threadIdx.x;
    if (i >= E) return;
    int s = src[i], d = dst[i];
    float v = g_as[s] + g_ad[d];
    float e = v > 0.f ? v : 0.2f * v;
    g_e[i] = e;
    atomicAdd(&g_rowsum[s], e);
}

// ---------------------------------------------------------------------------
// K3: out[src] += (e/rowsum[src] * edge_value) * msg[dst]
// IDENTICAL to R1: two edges per warp (16 lanes each), float4 LDG + RED.
// ---------------------------------------------------------------------------
__global__ void __launch_bounds__(256) k_scatter(
    const int* __restrict__ src, const int* __restrict__ dst,
    const float* __restrict__ ev, float* __restrict__ out, int E)
{
    int lane = threadIdx.x & 31;
    int g = lane >> 4;       // which edge of this warp's pair
    int gl = lane & 15;      // float4 chunk within the 64-channel row
    long long warpGlobal = (long long)(blockIdx.x * blockDim.x + threadIdx.x) >> 5;
    long long e = warpGlobal * 2 + g;
    bool active = (e < E);

    int s = 0, d = 0;
    float coef = 0.f;
    if (active && gl == 0) {
        s = src[e];
        d = dst[e];
        coef = g_e[e] / g_rowsum[s] * ev[e];
    }
    int srcLane = g * 16;
    s    = __shfl_sync(0xffffffffu, s, srcLane);
    d    = __shfl_sync(0xffffffffu, d, srcLane);
    coef = __shfl_sync(0xffffffffu, coef, srcLane);
    if (!active) return;

    const float4 m = *reinterpret_cast<const float4*>(&g_msg[(size_t)d * C + gl * 4]);
    float4 r = make_float4(coef * m.x, coef * m.y, coef * m.z, coef * m.w);
    red_add_v4(&out[(size_t)s * C + gl * 4], r);
}

extern "C" void kernel_launch(void* const* d_in, const int* in_sizes, int n_in,
                              void* d_out, int out_size)
{
    const float* x_source   = (const float*)d_in[0];   // [n, 64]
    const int*   edge_index = (const int*)d_in[1];     // [2, E]
    const float* edge_vals  = (const float*)d_in[2];   // [E]
    const float* W          = (const float*)d_in[3];   // [64, 64]
    const float* a          = (const float*)d_in[4];   // [128]
    float* out = (float*)d_out;

    int n = in_sizes[0] / C;
    int E = in_sizes[2];
    const int* src = edge_index;
    const int* dst = edge_index + E;

    // K1: 4 rows/warp, 8 warps -> 32 rows per block
    int blocks1 = (n + 31) / 32;
    k_gemm_alpha<<<blocks1, 256>>>(x_source, W, a, out, n);

    // K2: one thread/edge (identical to R1)
    int blocks2 = (E + 255) / 256;
    k_edge_e<<<blocks2, 256>>>(src, dst, E);

    // K3: two edges per warp -> 16 edges per 256-thread block (identical to R1)
    int blocks3 = (E + 15) / 16;
    k_scatter<<<blocks3, 256>>>(src, dst, edge_vals, out, E);
}

// round 7
// speedup vs baseline: 1.4748x; 1.2802x over previous
#include <cuda_runtime.h>
#include <cstdint>

#define N_CELLS_MAX 50048
#define N_EDGES_MAX 1600512
#define C 64
#define SCAN_B 512

// Scratch (allocation-free rule: __device__ globals)
__device__ float g_msg[N_CELLS_MAX * C];
__device__ float g_as[N_CELLS_MAX];
__device__ float g_ad[N_CELLS_MAX];
__device__ float g_rowsum[N_CELLS_MAX];
__device__ float g_e[N_EDGES_MAX];
__device__ int   g_deg[N_CELLS_MAX];
__device__ int   g_rowstart[N_CELLS_MAX + 1];
__device__ int   g_cursor[N_CELLS_MAX];
__device__ int   g_blockpart[256];
__device__ int2  g_csr[N_EDGES_MAX];   // (dst, bitcast coef)

// ---------------------------------------------------------------------------
// K1: msg = x @ W ; alpha via the EXACT R1/R6 fmaf+shfl sequence per row.
// Perf change only: 8 rows per warp (W LDS amortized 8x). Per-row float ops
// are literally the same sequence as the passing kernels.
// ---------------------------------------------------------------------------
__global__ void __launch_bounds__(256) k_gemm_alpha(
    const float* __restrict__ x, const float* __restrict__ W,
    const float* __restrict__ a, int n)
{
    __shared__ float Ws[C * C];
    __shared__ float As[2 * C];
    int tid = threadIdx.x;
    for (int i = tid; i < C * C; i += blockDim.x) Ws[i] = W[i];
    if (tid < 2 * C) As[tid] = a[tid];
    __syncthreads();

    int warp = tid >> 5, lane = tid & 31;
    int row0 = (blockIdx.x * 8 + warp) * 8;    // 8 consecutive rows per warp
    if (row0 >= n) return;

    float xr0[8], xr1[8];
    #pragma unroll
    for (int r = 0; r < 8; r++) {
        int row = row0 + r;
        if (row < n) {
            const float* xr = x + (size_t)row * C;
            xr0[r] = xr[lane];
            xr1[r] = xr[lane + 32];
        } else {
            xr0[r] = 0.f;
            xr1[r] = 0.f;
        }
    }

    float acc0[8], acc1[8];
    #pragma unroll
    for (int r = 0; r < 8; r++) { acc0[r] = 0.f; acc1[r] = 0.f; }

    #pragma unroll
    for (int k = 0; k < 32; k++) {
        float w0 = Ws[k * C + lane];
        float w1 = Ws[k * C + lane + 32];
        #pragma unroll
        for (int r = 0; r < 8; r++) {
            float xv = __shfl_sync(0xffffffffu, xr0[r], k);
            acc0[r] = fmaf(xv, w0, acc0[r]);
            acc1[r] = fmaf(xv, w1, acc1[r]);
        }
    }
    #pragma unroll
    for (int k = 0; k < 32; k++) {
        float w0 = Ws[(k + 32) * C + lane];
        float w1 = Ws[(k + 32) * C + lane + 32];
        #pragma unroll
        for (int r = 0; r < 8; r++) {
            float xv = __shfl_sync(0xffffffffu, xr1[r], k);
            acc0[r] = fmaf(xv, w0, acc0[r]);
            acc1[r] = fmaf(xv, w1, acc1[r]);
        }
    }

    #pragma unroll
    for (int r = 0; r < 8; r++) {
        int row = row0 + r;
        bool ok = (row < n);
        if (ok) {
            g_msg[(size_t)row * C + lane]      = acc0[r];
            g_msg[(size_t)row * C + lane + 32] = acc1[r];
        }
        // Same expression + same 32-lane butterfly as R1/R6.
        float s0 = acc0[r] * As[lane]     + acc1[r] * As[lane + 32];
        float s1 = acc0[r] * As[C + lane] + acc1[r] * As[C + lane + 32];
        #pragma unroll
        for (int o = 16; o > 0; o >>= 1) {
            s0 += __shfl_xor_sync(0xffffffffu, s0, o);
            s1 += __shfl_xor_sync(0xffffffffu, s1, o);
        }
        if (lane == 0 && ok) {
            g_as[row] = s0;
            g_ad[row] = s1;
            g_rowsum[row] = 0.f;
            g_deg[row] = 0;
        }
    }
}

// ---------------------------------------------------------------------------
// K2: e = LeakyReLU(as[src] + ad[dst]); store e; rowsum[src] += e
// IDENTICAL to R1/R6 (scalar, one thread per edge, same launch shape).
// Also bumps the degree histogram (integer, order-free).
// ---------------------------------------------------------------------------
__global__ void __launch_bounds__(256) k_edge_e(
    const int* __restrict__ src, const int* __restrict__ dst, int E)
{
    int i = blockIdx.x * blockDim.x + threadIdx.x;
    if (i >= E) return;
    int s = src[i], d = dst[i];
    float v = g_as[s] + g_ad[d];
    float e = v > 0.f ? v : 0.2f * v;
    g_e[i] = e;
    atomicAdd(&g_rowsum[s], e);
    atomicAdd(&g_deg[s], 1);
}

// ---------------------------------------------------------------------------
// Exclusive prefix scan of g_deg -> g_rowstart, g_cursor (3 stages)
// ---------------------------------------------------------------------------
__global__ void __launch_bounds__(SCAN_B) k_scan1(int n)
{
    __shared__ int sh[SCAN_B];
    int t = threadIdx.x;
    int gid = blockIdx.x * SCAN_B + t;
    sh[t] = (gid < n) ? g_deg[gid] : 0;
    __syncthreads();
    for (int o = SCAN_B / 2; o > 0; o >>= 1) {
        if (t < o) sh[t] += sh[t + o];
        __syncthreads();
    }
    if (t == 0) g_blockpart[blockIdx.x] = sh[0];
}

__global__ void k_scan2(int nb)
{
    if (threadIdx.x == 0 && blockIdx.x == 0) {
        int run = 0;
        for (int b = 0; b < nb; b++) {
            int v = g_blockpart[b];
            g_blockpart[b] = run;
            run += v;
        }
    }
}

__global__ void __launch_bounds__(SCAN_B) k_scan3(int n)
{
    __shared__ int sh[SCAN_B];
    int t = threadIdx.x;
    int gid = blockIdx.x * SCAN_B + t;
    int v = (gid < n) ? g_deg[gid] : 0;
    sh[t] = v;
    __syncthreads();
    for (int o = 1; o < SCAN_B; o <<= 1) {
        int xv = (t >= o) ? sh[t - o] : 0;
        __syncthreads();
        sh[t] += xv;
        __syncthreads();
    }
    int excl = sh[t] - v + g_blockpart[blockIdx.x];
    if (gid < n) {
        g_rowstart[gid] = excl;
        g_cursor[gid]   = excl;
        if (gid == n - 1) g_rowstart[n] = excl + v;
    }
}

// ---------------------------------------------------------------------------
// Build CSR with precomputed coef. coef uses the IDENTICAL expression the
// R6 K3 used: g_e[e] / g_rowsum[s] * ev[e]  (same values, since g_e and
// g_rowsum come from the unchanged K2).
// ---------------------------------------------------------------------------
__global__ void __launch_bounds__(256) k_build(
    const int* __restrict__ src, const int* __restrict__ dst,
    const float* __restrict__ ev, int E)
{
    int i = blockIdx.x * blockDim.x + threadIdx.x;
    if (i >= E) return;
    int s = src[i];
    float coef = g_e[i] / g_rowsum[s] * ev[i];
    int p = atomicAdd(&g_cursor[s], 1);
    g_csr[p] = make_int2(dst[i], __float_as_int(coef));
}

// ---------------------------------------------------------------------------
// K3: one warp per row: out[row] = sum_i coef_i * msg[dst_i], fp32 registers,
// no atomics. Each lane owns 2 channels (float2 gather -> 256B/warp/edge).
// Output-sum reorder only (per-term products identical) -> eps-level change.
// ---------------------------------------------------------------------------
__global__ void __launch_bounds__(256) k_row_aggregate(float* __restrict__ out, int n)
{
    int wid = threadIdx.x >> 5, lane = threadIdx.x & 31;
    int row = blockIdx.x * 8 + wid;
    if (row >= n) return;

    int beg = g_rowstart[row];
    int end = g_rowstart[row + 1];

    float a0 = 0.f, a1 = 0.f;
    int i = beg;
    // 4-way unroll: 4 independent csr loads -> MLP for the dependent gathers
    for (; i + 4 <= end; i += 4) {
        int2 p0 = g_csr[i];
        int2 p1 = g_csr[i + 1];
        int2 p2 = g_csr[i + 2];
        int2 p3 = g_csr[i + 3];
        float2 m0 = *(const float2*)&g_msg[(size_t)p0.x * C + lane * 2];
        float2 m1 = *(const float2*)&g_msg[(size_t)p1.x * C + lane * 2];
        float2 m2 = *(const float2*)&g_msg[(size_t)p2.x * C + lane * 2];
        float2 m3 = *(const float2*)&g_msg[(size_t)p3.x * C + lane * 2];
        float c0 = __int_as_float(p0.y);
        float c1 = __int_as_float(p1.y);
        float c2 = __int_as_float(p2.y);
        float c3 = __int_as_float(p3.y);
        a0 = fmaf(c0, m0.x, a0); a1 = fmaf(c0, m0.y, a1);
        a0 = fmaf(c1, m1.x, a0); a1 = fmaf(c1, m1.y, a1);
        a0 = fmaf(c2, m2.x, a0); a1 = fmaf(c2, m2.y, a1);
        a0 = fmaf(c3, m3.x, a0); a1 = fmaf(c3, m3.y, a1);
    }
    for (; i < end; i++) {
        int2 p = g_csr[i];
        float2 m = *(const float2*)&g_msg[(size_t)p.x * C + lane * 2];
        float c = __int_as_float(p.y);
        a0 = fmaf(c, m.x, a0);
        a1 = fmaf(c, m.y, a1);
    }
    *(float2*)&out[(size_t)row * C + lane * 2] = make_float2(a0, a1);
}

extern "C" void kernel_launch(void* const* d_in, const int* in_sizes, int n_in,
                              void* d_out, int out_size)
{
    const float* x_source   = (const float*)d_in[0];   // [n, 64]
    const int*   edge_index = (const int*)d_in[1];     // [2, E]
    const float* edge_vals  = (const float*)d_in[2];   // [E]
    const float* W          = (const float*)d_in[3];   // [64, 64]
    const float* a          = (const float*)d_in[4];   // [128]
    float* out = (float*)d_out;

    int n = in_sizes[0] / C;
    int E = in_sizes[2];
    const int* src = edge_index;
    const int* dst = edge_index + E;

    // K1: 8 rows/warp, 8 warps -> 64 rows per block
    int blocks1 = (n + 63) / 64;
    k_gemm_alpha<<<blocks1, 256>>>(x_source, W, a, n);

    // K2: one thread/edge (identical to R1/R6)
    int blocks2 = (E + 255) / 256;
    k_edge_e<<<blocks2, 256>>>(src, dst, E);

    // CSR build
    int nb = (n + SCAN_B - 1) / SCAN_B;
    k_scan1<<<nb, SCAN_B>>>(n);
    k_scan2<<<1, 32>>>(nb);
    k_scan3<<<nb, SCAN_B>>>(n);
    k_build<<<blocks2, 256>>>(src, dst, edge_vals, E);

    // K3: one warp per row
    int blocks3 = (n + 7) / 8;
    k_row_aggregate<<<blocks3, 256>>>(out, n);
}